// round 16
// baseline (speedup 1.0000x reference)
#include <cuda_runtime.h>
#include <cuda_bf16.h>
#include <math_constants.h>

// Problem constants (fixed shapes)
#define B_   8
#define C_   21
#define H_   512
#define W_   512
#define HW_  (H_ * W_)           // 262144 = 2^18
#define HW_SHIFT 18
#define NPIX (B_ * HW_)          // 2097152
#define MAX_M 0.5f
#define S_    30.0f

#define HGRID 512                // 512 blk * 256 thr * 4 int4 = 2M labels
#define LGRID (NPIX / 256)       // 8192 blocks, 1 pixel/thread (proven R3)

// Scratch (device globals — no allocations allowed). Written in graph order
// every launch, so replays are deterministic.
__device__ float  g_counts[C_];
__device__ float  g_mlist[C_];
__device__ double g_loss;

// ---------------------------------------------------------------------------
// Kernel 1: label histogram (R3 architecture + two validated micro-fixes):
//  - 4 batched int4 loads per thread (MLP=4 hides the DRAM latency);
//  - __match_any_sync leader aggregation: one conflict-free smem atomic per
//    distinct class per warp (no ATOMS multiplicity replays);
//  - atomics straight into g_counts (exact: totals < 2^24 in f32);
//  - block 0 zeroes g_loss and g_counts' stale values are avoided by
//    zero-init + reset discipline: g_counts is zeroed HERE before use via
//    the first-block trick being insufficient across blocks, so instead we
//    zero g_counts in block 0 and order it with a grid-wide assumption —
//    NOT safe. Therefore g_counts is zeroed by EVERY launch's mlist reader
//    instead: simplest safe scheme is atomicExch at consume time. To keep it
//    simple and proven: g_counts is reset by the finalize kernel of the
//    PREVIOUS replay, and initialized to zero at module load for the first.
// ---------------------------------------------------------------------------
__global__ __launch_bounds__(256) void hist_kernel(const int* __restrict__ target) {
    __shared__ int sh[8][C_];
    const int tid  = threadIdx.x;
    const int wid  = tid >> 5;
    const int lane = tid & 31;

    for (int i = tid; i < 8 * C_; i += 256) (&sh[0][0])[i] = 0;
    if (blockIdx.x == 0 && tid == 0) g_loss = 0.0;
    __syncthreads();

    const int4* t4 = reinterpret_cast<const int4*>(target);
    int4 a[4];
#pragma unroll
    for (int k = 0; k < 4; k++)
        a[k] = __ldg(t4 + blockIdx.x * 1024 + k * 256 + tid);

#define ACC_LABEL(val)                                                        \
    do {                                                                      \
        unsigned mk = __match_any_sync(0xffffffffu, (val));                   \
        if (lane == __ffs(mk) - 1)                                            \
            atomicAdd(&sh[wid][(val)], __popc(mk));                           \
    } while (0)

#pragma unroll
    for (int k = 0; k < 4; k++) {
        ACC_LABEL(a[k].x);
        ACC_LABEL(a[k].y);
        ACC_LABEL(a[k].z);
        ACC_LABEL(a[k].w);
    }
#undef ACC_LABEL
    __syncthreads();

    if (tid < C_) {
        int s = 0;
#pragma unroll
        for (int w = 0; w < 8; w++) s += sh[w][tid];
        if (s) atomicAdd(&g_counts[tid], (float)s);
    }
}

// ---------------------------------------------------------------------------
// Kernel 2: counts -> m_list (one warp, R3 verbatim)
// ---------------------------------------------------------------------------
__global__ void mlist_kernel() {
    int t = threadIdx.x;  // 32 threads
    float mi = 0.0f;
    float m  = -CUDART_INF_F;
    if (t < C_) {
        mi = rsqrtf(sqrtf(g_counts[t] + 1e-4f));
        m  = mi;
    }
#pragma unroll
    for (int o = 16; o > 0; o >>= 1)
        m = fmaxf(m, __shfl_xor_sync(0xffffffffu, m, o));
    if (t < C_) g_mlist[t] = mi * (MAX_M / m);
}

// ---------------------------------------------------------------------------
// Kernel 3: LDAM NLL — R3 verbatim (proven optimum: 33.1us, DRAM 71.7%,
// occ 91.4%). 1 pixel/thread, single pass, in-loop margin, static indexing
// keeps v[] in registers, __expf/__logf (fast regardless of compiler flags),
// per-block f64 atomic. No fences, no counters, no exp2f.
// ---------------------------------------------------------------------------
__global__ __launch_bounds__(256) void loss_kernel(const float* __restrict__ pred,
                                                   const int*   __restrict__ target) {
    int n  = blockIdx.x * 256 + threadIdx.x;   // exact grid: n < NPIX
    int b  = n >> HW_SHIFT;
    int hw = n & (HW_ - 1);
    const float* base = pred + (size_t)(b * C_) * HW_ + hw;

    int   l = target[n];
    float m = g_mlist[l];

    float v[C_];
    float maxv = -CUDART_INF_F;
    float vl   = 0.0f;
#pragma unroll
    for (int c = 0; c < C_; c++) {
        float x = __ldg(base + (size_t)c * HW_);
        if (c == l) x -= m;
        v[c] = x;
        maxv = fmaxf(maxv, x);
        if (c == l) vl = x;
    }

    float s = 0.0f;
#pragma unroll
    for (int c = 0; c < C_; c++)
        s += __expf(S_ * (v[c] - maxv));

    float nll = __logf(s) + S_ * (maxv - vl);

#pragma unroll
    for (int o = 16; o > 0; o >>= 1)
        nll += __shfl_xor_sync(0xffffffffu, nll, o);

    __shared__ float warp_sums[8];
    int lane = threadIdx.x & 31;
    int wid  = threadIdx.x >> 5;
    if (lane == 0) warp_sums[wid] = nll;
    __syncthreads();

    if (wid == 0) {
        float x = (lane < 8) ? warp_sums[lane] : 0.0f;
#pragma unroll
        for (int o = 4; o > 0; o >>= 1)
            x += __shfl_xor_sync(0xffffffffu, x, o);
        if (lane == 0) atomicAdd(&g_loss, (double)x);
    }
}

// ---------------------------------------------------------------------------
// Kernel 4: finalize — mean + reset g_counts for the next graph replay
// (g_counts is consumed by mlist strictly before this kernel runs, and the
// next replay's hist accumulates on top of the zeros written here).
// ---------------------------------------------------------------------------
__global__ void finalize_kernel(float* __restrict__ out) {
    int t = threadIdx.x;
    if (t == 0) out[0] = (float)(g_loss * (1.0 / (double)NPIX));
    if (t < C_) g_counts[t] = 0.0f;
}

// ---------------------------------------------------------------------------
extern "C" void kernel_launch(void* const* d_in, const int* in_sizes, int n_in,
                              void* d_out, int out_size) {
    const float* pred   = (const float*)d_in[0];
    const int*   target = (const int*)d_in[1];
    float*       out    = (float*)d_out;

    hist_kernel<<<HGRID, 256>>>(target);
    mlist_kernel<<<1, 32>>>();
    loss_kernel<<<LGRID, 256>>>(pred, target);
    finalize_kernel<<<1, 32>>>(out);
}

// round 17
// speedup vs baseline: 1.1598x; 1.1598x over previous
#include <cuda_runtime.h>
#include <cuda_bf16.h>
#include <math_constants.h>

// Problem constants (fixed shapes)
#define B_   8
#define C_   21
#define H_   512
#define W_   512
#define HW_  (H_ * W_)           // 262144 = 2^18
#define HW_SHIFT 18
#define NPIX (B_ * HW_)          // 2097152
#define MAX_M 0.5f
#define S_    30.0f

#define HGRID (NPIX / 4 / 256)   // 2048 blocks: one int4 per thread (R8 best)
#define LGRID (NPIX / 256)       // 8192 blocks: one pixel per thread (R3 best)

// Scratch (device globals — no allocations allowed).
// g_counts starts zero (module load) and is re-zeroed by finalize each
// launch, so graph replays are deterministic. g_loss is zeroed by hist.
__device__ float  g_counts[C_];
__device__ float  g_mlist[C_];
__device__ double g_loss;

// ---------------------------------------------------------------------------
// Kernel 1: label histogram — R8's empirically best variant: 2048 blocks,
// one int4 per thread, per-warp smem sub-histograms, plain atomics.
// Block 0 zeroes g_loss (consumed only by the strictly-later loss kernel).
// ---------------------------------------------------------------------------
__global__ __launch_bounds__(256) void hist_kernel(const int* __restrict__ target) {
    __shared__ int sh[8][C_];
    const int tid = threadIdx.x;
    const int wid = tid >> 5;

    for (int i = tid; i < 8 * C_; i += 256) (&sh[0][0])[i] = 0;
    if (blockIdx.x == 0 && tid == 0) g_loss = 0.0;
    __syncthreads();

    int4 v = __ldg(reinterpret_cast<const int4*>(target) + blockIdx.x * 256 + tid);
    atomicAdd(&sh[wid][v.x], 1);
    atomicAdd(&sh[wid][v.y], 1);
    atomicAdd(&sh[wid][v.z], 1);
    atomicAdd(&sh[wid][v.w], 1);
    __syncthreads();

    if (tid < C_) {
        int s = 0;
#pragma unroll
        for (int w = 0; w < 8; w++) s += sh[w][tid];
        if (s) atomicAdd(&g_counts[tid], (float)s);
    }
}

// ---------------------------------------------------------------------------
// Kernel 2: counts -> m_list (one warp, R3 verbatim)
// ---------------------------------------------------------------------------
__global__ void mlist_kernel() {
    int t = threadIdx.x;  // 32 threads
    float mi = 0.0f;
    float m  = -CUDART_INF_F;
    if (t < C_) {
        mi = rsqrtf(sqrtf(g_counts[t] + 1e-4f));
        m  = mi;
    }
#pragma unroll
    for (int o = 16; o > 0; o >>= 1)
        m = fmaxf(m, __shfl_xor_sync(0xffffffffu, m, o));
    if (t < C_) g_mlist[t] = mi * (MAX_M / m);
}

// ---------------------------------------------------------------------------
// Kernel 3: LDAM NLL — R3 verbatim body (proven optimum: DRAM 71.7%,
// occ 91.4%), with ONE change: pred loads use __ldcs (streaming/evict-first).
// pred is a 176MB single-pass stream through a 126MB L2 — evict-first stops
// it from thrashing resident lines and should lift achieved HBM bandwidth.
// Everything else untouched: 1 pixel/thread, single pass, in-loop margin,
// static indexing keeps v[] in registers, __expf/__logf, per-block f64 atomic.
// ---------------------------------------------------------------------------
__global__ __launch_bounds__(256) void loss_kernel(const float* __restrict__ pred,
                                                   const int*   __restrict__ target) {
    int n  = blockIdx.x * 256 + threadIdx.x;   // exact grid: n < NPIX
    int b  = n >> HW_SHIFT;
    int hw = n & (HW_ - 1);
    const float* base = pred + (size_t)(b * C_) * HW_ + hw;

    int   l = target[n];
    float m = g_mlist[l];

    float v[C_];
    float maxv = -CUDART_INF_F;
    float vl   = 0.0f;
#pragma unroll
    for (int c = 0; c < C_; c++) {
        float x = __ldcs(base + (size_t)c * HW_);   // streaming, evict-first
        if (c == l) x -= m;
        v[c] = x;
        maxv = fmaxf(maxv, x);
        if (c == l) vl = x;
    }

    float s = 0.0f;
#pragma unroll
    for (int c = 0; c < C_; c++)
        s += __expf(S_ * (v[c] - maxv));

    float nll = __logf(s) + S_ * (maxv - vl);

#pragma unroll
    for (int o = 16; o > 0; o >>= 1)
        nll += __shfl_xor_sync(0xffffffffu, nll, o);

    __shared__ float warp_sums[8];
    int lane = threadIdx.x & 31;
    int wid  = threadIdx.x >> 5;
    if (lane == 0) warp_sums[wid] = nll;
    __syncthreads();

    if (wid == 0) {
        float x = (lane < 8) ? warp_sums[lane] : 0.0f;
#pragma unroll
        for (int o = 4; o > 0; o >>= 1)
            x += __shfl_xor_sync(0xffffffffu, x, o);
        if (lane == 0) atomicAdd(&g_loss, (double)x);
    }
}

// ---------------------------------------------------------------------------
// Kernel 4: finalize — mean + reset g_counts for the next graph replay
// (mlist consumed g_counts strictly earlier in this launch; the next
// replay's hist accumulates onto the zeros written here).
// ---------------------------------------------------------------------------
__global__ void finalize_kernel(float* __restrict__ out) {
    int t = threadIdx.x;
    if (t == 0) out[0] = (float)(g_loss * (1.0 / (double)NPIX));
    if (t < C_) g_counts[t] = 0.0f;
}

// ---------------------------------------------------------------------------
extern "C" void kernel_launch(void* const* d_in, const int* in_sizes, int n_in,
                              void* d_out, int out_size) {
    const float* pred   = (const float*)d_in[0];
    const int*   target = (const int*)d_in[1];
    float*       out    = (float*)d_out;

    hist_kernel<<<HGRID, 256>>>(target);
    mlist_kernel<<<1, 32>>>();
    loss_kernel<<<LGRID, 256>>>(pred, target);
    finalize_kernel<<<1, 32>>>(out);
}